// round 7
// baseline (speedup 1.0000x reference)
#include <cuda_runtime.h>
#include <cuda_bf16.h>

// ---------------------------------------------------------------------------
// RtoVMainModel. Convs per image in smem (packed f32x2 FMA); linear heads
// collapsed at runtime (S=W3@W2, T2=S@W1, We=ew4@T2). k_main computes shapes
// AND all 4 experts' 6 outputs per image (g_eo); k_out is a trivial gather.
// d_out layout: [shapes (B*4) | out (B*6)] float32
// ---------------------------------------------------------------------------

#define B_TOTAL 16384
typedef unsigned long long u64;

__device__ __forceinline__ u64 pk(float lo, float hi) {
    u64 r; asm("mov.b64 %0, {%1, %2};" : "=l"(r) : "f"(lo), "f"(hi)); return r;
}
__device__ __forceinline__ void upk(u64 p, float& lo, float& hi) {
    asm("mov.b64 {%0, %1}, %2;" : "=f"(lo), "=f"(hi) : "l"(p));
}
__device__ __forceinline__ u64 fma2(u64 a, u64 b, u64 c) {
    u64 d; asm("fma.rn.f32x2 %0, %1, %2, %3;" : "=l"(d) : "l"(a), "l"(b), "l"(c)); return d;
}

// scratch (device globals: no allocation allowed)
__device__ float g_T2[5 * 10 * 400];     // chain 0 = shapes head (10x400)
__device__ float g_b3[5 * 10];
__device__ float g_We[4 * 6 * 400];      // expert collapsed rows
__device__ float g_be[4 * 6];            // expert collapsed bias (incl eb4)
__device__ float g_eo[B_TOTAL * 24];     // all-expert outputs per image
__device__ int   g_last[6 * 32];         // routing slots [col][b&31]

// ---------------------------------------------------------------------------
// Prologue: grid = 5 chains x 16 column-chunks = 80 blocks, 256 threads.
// Also builds g_We (expert chains) and g_be from its local T2 slice.
// ---------------------------------------------------------------------------
__global__ void __launch_bounds__(256)
kc_prep(const float* __restrict__ sw1, const float* __restrict__ sb1,
        const float* __restrict__ sw2, const float* __restrict__ sb2,
        const float* __restrict__ sw3, const float* __restrict__ sb3,
        const float* __restrict__ ew1, const float* __restrict__ eb1,
        const float* __restrict__ ew2, const float* __restrict__ eb2,
        const float* __restrict__ ew3, const float* __restrict__ eb3,
        const float* __restrict__ ew4, const float* __restrict__ eb4) {
    __shared__ float sW2[84 * 120];
    __shared__ float sW1c[120 * 25];
    __shared__ float sS[10 * 120];
    __shared__ float sb2p[84];
    __shared__ float sT2c[10 * 25];
    __shared__ float sb3l[10];

    int chain = blockIdx.x >> 4, chunk = blockIdx.x & 15;
    int j0 = chunk * 25;
    int tid = threadIdx.x;
    if (blockIdx.x == 0 && tid < 192) g_last[tid] = -1;

    const float* W1 = chain ? (ew1 + (chain - 1) * 120 * 400) : sw1;
    const float* W2 = chain ? (ew2 + (chain - 1) * 84 * 120) : sw2;
    const float* W3 = chain ? (ew3 + (chain - 1) * 10 * 84) : sw3;
    const float* b1 = chain ? (eb1 + (chain - 1) * 120) : sb1;
    const float* b2 = chain ? (eb2 + (chain - 1) * 84) : sb2;
    const float* b3 = chain ? (eb3 + (chain - 1) * 10) : sb3;

    for (int i = tid; i < 10080; i += 256) sW2[i] = W2[i];
    for (int i = tid; i < 3000; i += 256) {
        int row = i / 25, col = i - row * 25;
        sW1c[i] = W1[row * 400 + j0 + col];
    }
    __syncthreads();

    for (int p = tid; p < 1200; p += 256) {
        int o = p / 120, k = p - o * 120;
        float s = 0.f;
        const float* w3r = W3 + o * 84;
        for (int m = 0; m < 84; m++) s = fmaf(w3r[m], sW2[m * 120 + k], s);
        sS[p] = s;
    }
    if (tid < 84) {
        float s = b2[tid];
        const float* r = sW2 + tid * 120;
        for (int k = 0; k < 120; k++) s = fmaf(r[k], b1[k], s);
        sb2p[tid] = s;
    }
    __syncthreads();

    if (tid < 10) {
        float s = b3[tid];
        const float* r = W3 + tid * 84;
        for (int m = 0; m < 84; m++) s = fmaf(r[m], sb2p[m], s);
        sb3l[tid] = s;
        if (chunk == 0) g_b3[chain * 10 + tid] = s;
    }

    if (tid < 250) {
        int o = tid / 25, jj = tid - o * 25;
        float s = 0.f;
        const float* sr = sS + o * 120;
        for (int k = 0; k < 120; k++) s = fmaf(sr[k], sW1c[k * 25 + jj], s);
        g_T2[(chain * 10 + o) * 400 + j0 + jj] = s;
        sT2c[o * 25 + jj] = s;
    }
    __syncthreads();

    // expert chains: We slice + (chunk 0) collapsed bias
    if (chain >= 1) {
        int e = chain - 1;
        if (tid < 150) {
            int c = tid / 25, jj = tid - c * 25;
            float s = 0.f;
            const float* w4r = ew4 + e * 60 + c * 10;
#pragma unroll
            for (int k = 0; k < 10; k++) s = fmaf(w4r[k], sT2c[k * 25 + jj], s);
            g_We[(e * 6 + c) * 400 + j0 + jj] = s;
        }
        if (chunk == 0 && tid < 6) {
            float s = eb4[e * 6 + tid];
            const float* w4r = ew4 + e * 60 + tid * 10;
#pragma unroll
            for (int k = 0; k < 10; k++) s = fmaf(w4r[k], sb3l[k], s);
            g_be[e * 6 + tid] = s;
        }
    }
}

// ---------------------------------------------------------------------------
// Main fused kernel: one block (192 threads) per TWO images.
// ---------------------------------------------------------------------------
__global__ void __launch_bounds__(192, 3)
k_main(const float* __restrict__ x,
       const float* __restrict__ c1w, const float* __restrict__ c1b,
       const float* __restrict__ c2w, const float* __restrict__ c2b,
       const float* __restrict__ sw4, const float* __restrict__ sb4,
       float* __restrict__ out) {
    __shared__ __align__(16) float  s_x[3 * 32 * 36];
    __shared__ __align__(16) float  s_y1[2][6 * 14 * 20];
    __shared__ __align__(16) float2 s_w1p[450];
    __shared__ __align__(16) float2 s_w2p[2400];
    __shared__ float s_b1[6], s_b2[16];
    __shared__ __align__(16) float s_xf[2][400];
    __shared__ float hs[2][10];

    int b0i = blockIdx.x * 2, tid = threadIdx.x;

    // ---- load weights + image 0 ----
    {
        const float4* xg = (const float4*)(x + (size_t)b0i * 3072);
        for (int g = tid; g < 768; g += 192) {
            float4 v = xg[g];
            int gr = g >> 3, c4 = g & 7;
            *(float4*)(s_x + gr * 36 + c4 * 4) = v;
        }
    }
    for (int i = tid; i < 450; i += 192)  { float w = c1w[i]; s_w1p[i] = make_float2(w, w); }
    for (int i = tid; i < 2400; i += 192) { float w = c2w[i]; s_w2p[i] = make_float2(w, w); }
    if (tid < 6)  s_b1[tid] = c1b[tid];
    if (tid < 16) s_b2[tid] = c2b[tid];
    __syncthreads();

    // ---- conv1 per image ----
#pragma unroll 1
    for (int img = 0; img < 2; img++) {
        if (tid < 168) {
            int ch = tid / 28, rem = tid % 28, py = rem >> 1, h = rem & 1;
            u64 acc0[7], acc1[7];
#pragma unroll
            for (int j = 0; j < 7; j++) { acc0[j] = 0ull; acc1[j] = 0ull; }
            const float* xbase = s_x + (2 * py) * 36 + 14 * h;
#pragma unroll 1
            for (int ic = 0; ic < 3; ic++) {
                const float2* wb = s_w1p + (ch * 3 + ic) * 25;
                u64 wv[5][5];
#pragma unroll
                for (int xr = 0; xr < 6; xr++) {
                    const u64* rp = (const u64*)(xbase + ic * (32 * 36) + xr * 36);
                    u64 pe[9]; float xl[9], xh[9];
#pragma unroll
                    for (int m = 0; m < 9; m++) { pe[m] = rp[m]; upk(pe[m], xl[m], xh[m]); }
                    u64 po[8];
#pragma unroll
                    for (int m = 0; m < 8; m++) po[m] = pk(xh[m], xl[m + 1]);
                    if (xr < 5) {
#pragma unroll
                        for (int k = 0; k < 5; k++) wv[xr][k] = *(const u64*)&wb[xr * 5 + k];
#pragma unroll
                        for (int kx = 0; kx < 5; kx++) {
                            u64 w = wv[xr][kx];
#pragma unroll
                            for (int j = 0; j < 7; j++)
                                acc0[j] = fma2(w, (kx & 1) ? po[j + (kx >> 1)] : pe[j + (kx >> 1)], acc0[j]);
                        }
                    }
                    if (xr >= 1) {
#pragma unroll
                        for (int kx = 0; kx < 5; kx++) {
                            u64 w = wv[xr - 1][kx];
#pragma unroll
                            for (int j = 0; j < 7; j++)
                                acc1[j] = fma2(w, (kx & 1) ? po[j + (kx >> 1)] : pe[j + (kx >> 1)], acc1[j]);
                        }
                    }
                }
            }
            float bv = s_b1[ch];
            float* yrow = s_y1[img] + (ch * 14 + py) * 20 + 7 * h;
#pragma unroll
            for (int j = 0; j < 7; j++) {
                float a0, a1, c0, c1;
                upk(acc0[j], a0, a1); upk(acc1[j], c0, c1);
                float m = fmaxf(fmaxf(a0, a1), fmaxf(c0, c1)) + bv;
                yrow[j] = fmaxf(m, 0.f);
            }
        }
        __syncthreads();
        if (img == 0) {
            const float4* xg = (const float4*)(x + (size_t)(b0i + 1) * 3072);
            for (int g = tid; g < 768; g += 192) {
                float4 v = xg[g];
                int gr = g >> 3, c4 = g & 7;
                *(float4*)(s_x + gr * 36 + c4 * 4) = v;
            }
            __syncthreads();
        }
    }

    // ---- conv2 full depth: 160 tasks = (img, ch, pooled row) ----
    if (tid < 160) {
        int img = tid / 80;
        int r2 = tid % 80, ch2 = r2 / 5, py2 = r2 % 5;
        u64 b0[5], b1[5];
#pragma unroll
        for (int j = 0; j < 5; j++) { b0[j] = 0ull; b1[j] = 0ull; }
#pragma unroll 1
        for (int ic = 0; ic < 6; ic++) {
            const float2* wb = s_w2p + (ch2 * 6 + ic) * 25;
            u64 wv[5][5];
#pragma unroll
            for (int xr = 0; xr < 6; xr++) {
                const u64* rp = (const u64*)(s_y1[img] + (ic * 14 + 2 * py2 + xr) * 20);
                u64 pe[7]; float xl[7], xh[7];
#pragma unroll
                for (int m = 0; m < 7; m++) { pe[m] = rp[m]; upk(pe[m], xl[m], xh[m]); }
                u64 po[6];
#pragma unroll
                for (int m = 0; m < 6; m++) po[m] = pk(xh[m], xl[m + 1]);
                if (xr < 5) {
#pragma unroll
                    for (int k = 0; k < 5; k++) wv[xr][k] = *(const u64*)&wb[xr * 5 + k];
#pragma unroll
                    for (int kx = 0; kx < 5; kx++) {
                        u64 w = wv[xr][kx];
#pragma unroll
                        for (int j = 0; j < 5; j++)
                            b0[j] = fma2(w, (kx & 1) ? po[j + (kx >> 1)] : pe[j + (kx >> 1)], b0[j]);
                    }
                }
                if (xr >= 1) {
#pragma unroll
                    for (int kx = 0; kx < 5; kx++) {
                        u64 w = wv[xr - 1][kx];
#pragma unroll
                        for (int j = 0; j < 5; j++)
                            b1[j] = fma2(w, (kx & 1) ? po[j + (kx >> 1)] : pe[j + (kx >> 1)], b1[j]);
                    }
                }
            }
        }
        float bv = s_b2[ch2];
        float* xfp = s_xf[img] + ch2 * 25 + py2 * 5;
#pragma unroll
        for (int j = 0; j < 5; j++) {
            float a0, a1, c0, c1;
            upk(b0[j], a0, a1); upk(b1[j], c0, c1);
            float v = fmaxf(fmaxf(a0, a1), fmaxf(c0, c1)) + bv;
            xfp[j] = fmaxf(v, 0.f);
        }
    }
    __syncthreads();

    // ---- fused head: 40 row-slots x 4 lanes = 160 threads (5 FULL warps;
    //      rows 34-39 are dummies so every shfl warp is fully populated) ----
    if (tid < 160) {
        int o = tid >> 2, l = tid & 3;
        bool live = (o < 34);
        const float* wr = (o < 10) ? (g_T2 + o * 400)
                         : (live ? (g_We + (o - 10) * 400) : g_T2);  // dummy: row 0
        const float4* wv4 = (const float4*)(wr + l * 4);
#pragma unroll 1
        for (int img = 0; img < 2; img++) {
            const float4* xf4 = (const float4*)(s_xf[img] + l * 4);
            float s = 0.f;
#pragma unroll
            for (int it = 0; it < 25; it++) {
                float4 wq = wv4[it * 4];
                float4 xq = xf4[it * 4];
                s = fmaf(wq.x, xq.x, s);
                s = fmaf(wq.y, xq.y, s);
                s = fmaf(wq.z, xq.z, s);
                s = fmaf(wq.w, xq.w, s);
            }
            s += __shfl_down_sync(0xffffffffu, s, 2, 4);
            s += __shfl_down_sync(0xffffffffu, s, 1, 4);
            if (l == 0 && live) {
                if (o < 10) hs[img][o] = s + g_b3[o];
                else g_eo[(size_t)(b0i + img) * 24 + (o - 10)] = s + g_be[o - 10];
            }
        }
    }
    __syncthreads();

    // ---- shapes + argmax + routing: 2 threads (one per image) ----
    if (tid < 2) {
        int img = tid, b = b0i + img;
        float sh[4];
#pragma unroll
        for (int c = 0; c < 4; c++) {
            float s = sb4[c];
#pragma unroll
            for (int o = 0; o < 10; o++)
                s = fmaf(fmaxf(hs[img][o], 0.f), sw4[c * 10 + o], s);
            sh[c] = s;
            out[(size_t)b * 4 + c] = s;
        }
        int pred = 0;
        float best = sh[0];
#pragma unroll
        for (int k = 1; k < 4; k++)
            if (sh[k] > best) { best = sh[k]; pred = k; }
        const int widths[4] = {3, 5, 6, 5};
        int w = widths[pred];
        int val = (b << 2) | pred;
        int slot = b & 31;
        for (int c = 0; c < w; c++) atomicMax(&g_last[c * 32 + slot], val);
    }
}

// ---------------------------------------------------------------------------
// Gather: out[b][c] = covered(c) ? g_eo[b][e_j[c]*6+c] : 0
// grid 512 x 192 threads (32 images x 6 cols per block)
// ---------------------------------------------------------------------------
__global__ void __launch_bounds__(192)
k_out(float* __restrict__ out) {
    __shared__ int psel[6];
    int tid = threadIdx.x;
    if (tid < 6) {
        int mx = -1;
#pragma unroll
        for (int s = 0; s < 32; s++) mx = max(mx, g_last[tid * 32 + s]);
        psel[tid] = mx;
    }
    __syncthreads();
    int r = tid / 6, c = tid - r * 6;
    int b = blockIdx.x * 32 + r;
    int p = psel[c];
    float v = (p >= 0) ? g_eo[(size_t)b * 24 + (p & 3) * 6 + c] : 0.f;
    out[(size_t)B_TOTAL * 4 + (size_t)b * 6 + c] = v;
}

// ---------------------------------------------------------------------------
extern "C" void kernel_launch(void* const* d_in, const int* in_sizes, int n_in,
                              void* d_out, int out_size) {
    const float* x    = (const float*)d_in[0];
    const float* c1w  = (const float*)d_in[1];
    const float* c1b  = (const float*)d_in[2];
    const float* c2w  = (const float*)d_in[3];
    const float* c2b  = (const float*)d_in[4];
    const float* sw1  = (const float*)d_in[5];
    const float* sb1  = (const float*)d_in[6];
    const float* sw2  = (const float*)d_in[7];
    const float* sb2  = (const float*)d_in[8];
    const float* sw3  = (const float*)d_in[9];
    const float* sb3  = (const float*)d_in[10];
    const float* sw4  = (const float*)d_in[11];
    const float* sb4  = (const float*)d_in[12];
    const float* ew1  = (const float*)d_in[13];
    const float* eb1  = (const float*)d_in[14];
    const float* ew2  = (const float*)d_in[15];
    const float* eb2  = (const float*)d_in[16];
    const float* ew3  = (const float*)d_in[17];
    const float* eb3  = (const float*)d_in[18];
    const float* ew4  = (const float*)d_in[19];
    const float* eb4  = (const float*)d_in[20];
    float* out = (float*)d_out;

    kc_prep<<<80, 256>>>(sw1, sb1, sw2, sb2, sw3, sb3,
                         ew1, eb1, ew2, eb2, ew3, eb3, ew4, eb4);
    k_main<<<B_TOTAL / 2, 192>>>(x, c1w, c1b, c2w, c2b, sw4, sb4, out);
    k_out<<<B_TOTAL / 32, 192>>>(out);
}

// round 9
// speedup vs baseline: 1.0691x; 1.0691x over previous
#include <cuda_runtime.h>
#include <cuda_bf16.h>

// ---------------------------------------------------------------------------
// RtoVMainModel. Convs per image in smem (packed f32x2 FMA); linear heads
// collapsed at runtime (S=W3@W2, T2=S@W1, We=ew4@T2 in kc_prep).
// k_main: 2 images per block, both x resident; conv1 = 336 tasks via
// strided loop (no reload phase); conv2 = 160 tasks; shapes head; routing.
// k_out: gather + 6x400 dots with smem-cached selected expert rows.
// d_out layout: [shapes (B*4) | out (B*6)] float32
// ---------------------------------------------------------------------------

#define B_TOTAL 16384
typedef unsigned long long u64;

__device__ __forceinline__ u64 pk(float lo, float hi) {
    u64 r; asm("mov.b64 %0, {%1, %2};" : "=l"(r) : "f"(lo), "f"(hi)); return r;
}
__device__ __forceinline__ void upk(u64 p, float& lo, float& hi) {
    asm("mov.b64 {%0, %1}, %2;" : "=f"(lo), "=f"(hi) : "l"(p));
}
__device__ __forceinline__ u64 fma2(u64 a, u64 b, u64 c) {
    u64 d; asm("fma.rn.f32x2 %0, %1, %2, %3;" : "=l"(d) : "l"(a), "l"(b), "l"(c)); return d;
}

// scratch (device globals: no allocation allowed)
__device__ float g_T2[5 * 10 * 400];     // chain 0 = shapes head (10x400)
__device__ float g_b3[5 * 10];
__device__ float g_We[4 * 6 * 400];      // expert collapsed rows
__device__ float g_be[4 * 6];            // expert collapsed bias (incl eb4)
__device__ float g_xf[B_TOTAL * 400];    // conv features
__device__ int   g_last[6 * 32];         // routing slots [col][b&31]

// ---------------------------------------------------------------------------
// Prologue: grid = 5 chains x 16 column-chunks = 80 blocks, 256 threads.
// ---------------------------------------------------------------------------
__global__ void __launch_bounds__(256)
kc_prep(const float* __restrict__ sw1, const float* __restrict__ sb1,
        const float* __restrict__ sw2, const float* __restrict__ sb2,
        const float* __restrict__ sw3, const float* __restrict__ sb3,
        const float* __restrict__ ew1, const float* __restrict__ eb1,
        const float* __restrict__ ew2, const float* __restrict__ eb2,
        const float* __restrict__ ew3, const float* __restrict__ eb3,
        const float* __restrict__ ew4, const float* __restrict__ eb4) {
    __shared__ float sW2[84 * 120];
    __shared__ float sW1c[120 * 25];
    __shared__ float sS[10 * 120];
    __shared__ float sb2p[84];
    __shared__ float sT2c[10 * 25];
    __shared__ float sb3l[10];

    int chain = blockIdx.x >> 4, chunk = blockIdx.x & 15;
    int j0 = chunk * 25;
    int tid = threadIdx.x;
    if (blockIdx.x == 0 && tid < 192) g_last[tid] = -1;

    const float* W1 = chain ? (ew1 + (chain - 1) * 120 * 400) : sw1;
    const float* W2 = chain ? (ew2 + (chain - 1) * 84 * 120) : sw2;
    const float* W3 = chain ? (ew3 + (chain - 1) * 10 * 84) : sw3;
    const float* b1 = chain ? (eb1 + (chain - 1) * 120) : sb1;
    const float* b2 = chain ? (eb2 + (chain - 1) * 84) : sb2;
    const float* b3 = chain ? (eb3 + (chain - 1) * 10) : sb3;

    for (int i = tid; i < 10080; i += 256) sW2[i] = W2[i];
    for (int i = tid; i < 3000; i += 256) {
        int row = i / 25, col = i - row * 25;
        sW1c[i] = W1[row * 400 + j0 + col];
    }
    __syncthreads();

    for (int p = tid; p < 1200; p += 256) {
        int o = p / 120, k = p - o * 120;
        float s = 0.f;
        const float* w3r = W3 + o * 84;
        for (int m = 0; m < 84; m++) s = fmaf(w3r[m], sW2[m * 120 + k], s);
        sS[p] = s;
    }
    if (tid < 84) {
        float s = b2[tid];
        const float* r = sW2 + tid * 120;
        for (int k = 0; k < 120; k++) s = fmaf(r[k], b1[k], s);
        sb2p[tid] = s;
    }
    __syncthreads();

    if (tid < 10) {
        float s = b3[tid];
        const float* r = W3 + tid * 84;
        for (int m = 0; m < 84; m++) s = fmaf(r[m], sb2p[m], s);
        sb3l[tid] = s;
        if (chunk == 0) g_b3[chain * 10 + tid] = s;
    }

    if (tid < 250) {
        int o = tid / 25, jj = tid - o * 25;
        float s = 0.f;
        const float* sr = sS + o * 120;
        for (int k = 0; k < 120; k++) s = fmaf(sr[k], sW1c[k * 25 + jj], s);
        g_T2[(chain * 10 + o) * 400 + j0 + jj] = s;
        sT2c[o * 25 + jj] = s;
    }
    __syncthreads();

    if (chain >= 1) {
        int e = chain - 1;
        if (tid < 150) {
            int c = tid / 25, jj = tid - c * 25;
            float s = 0.f;
            const float* w4r = ew4 + e * 60 + c * 10;
#pragma unroll
            for (int k = 0; k < 10; k++) s = fmaf(w4r[k], sT2c[k * 25 + jj], s);
            g_We[(e * 6 + c) * 400 + j0 + jj] = s;
        }
        if (chunk == 0 && tid < 6) {
            float s = eb4[e * 6 + tid];
            const float* w4r = ew4 + e * 60 + tid * 10;
#pragma unroll
            for (int k = 0; k < 10; k++) s = fmaf(w4r[k], sb3l[k], s);
            g_be[e * 6 + tid] = s;
        }
    }
}

// ---------------------------------------------------------------------------
// Main fused kernel: one block (192 threads) per TWO images; both x buffers
// resident; conv1 covers 336 tasks with a strided loop (no barrier inside).
// ---------------------------------------------------------------------------
__global__ void __launch_bounds__(192, 3)
k_main(const float* __restrict__ x,
       const float* __restrict__ c1w, const float* __restrict__ c1b,
       const float* __restrict__ c2w, const float* __restrict__ c2b,
       const float* __restrict__ sw4, const float* __restrict__ sb4,
       float* __restrict__ out) {
    __shared__ __align__(16) float  s_x[2][3 * 32 * 36];
    __shared__ __align__(16) float  s_y1[2][6 * 14 * 20];
    __shared__ __align__(16) float2 s_w1p[450];
    __shared__ __align__(16) float2 s_w2p[2400];
    __shared__ float s_b1[6], s_b2[16];
    __shared__ __align__(16) float s_xf[2][400];
    __shared__ float hs[2][10];

    int b0i = blockIdx.x * 2, tid = threadIdx.x;

    // ---- load both images + weights ----
    {
        const float4* xg = (const float4*)(x + (size_t)b0i * 3072);
        for (int g = tid; g < 1536; g += 192) {
            float4 v = xg[g];
            int im = g / 768, q = g - im * 768;
            int gr = q >> 3, c4 = q & 7;
            *(float4*)(s_x[im] + gr * 36 + c4 * 4) = v;
        }
    }
    for (int i = tid; i < 450; i += 192)  { float w = c1w[i]; s_w1p[i] = make_float2(w, w); }
    for (int i = tid; i < 2400; i += 192) { float w = c2w[i]; s_w2p[i] = make_float2(w, w); }
    if (tid < 6)  s_b1[tid] = c1b[tid];
    if (tid < 16) s_b2[tid] = c2b[tid];
    __syncthreads();

    // ---- conv1 + relu + pool: 336 tasks = (img, ch, pooled row, half) ----
#pragma unroll 1
    for (int t = tid; t < 336; t += 192) {
        int img = t / 168, rem = t % 168;
        int ch = rem / 28, rr = rem % 28, py = rr >> 1, h = rr & 1;
        u64 acc0[7], acc1[7];
#pragma unroll
        for (int j = 0; j < 7; j++) { acc0[j] = 0ull; acc1[j] = 0ull; }
        const float* xbase = s_x[img] + (2 * py) * 36 + 14 * h;
#pragma unroll 1
        for (int ic = 0; ic < 3; ic++) {
            const float2* wb = s_w1p + (ch * 3 + ic) * 25;
            u64 wv[5][5];
#pragma unroll
            for (int xr = 0; xr < 6; xr++) {
                const u64* rp = (const u64*)(xbase + ic * (32 * 36) + xr * 36);
                u64 pe[9]; float xl[9], xh[9];
#pragma unroll
                for (int m = 0; m < 9; m++) { pe[m] = rp[m]; upk(pe[m], xl[m], xh[m]); }
                u64 po[8];
#pragma unroll
                for (int m = 0; m < 8; m++) po[m] = pk(xh[m], xl[m + 1]);
                if (xr < 5) {
#pragma unroll
                    for (int k = 0; k < 5; k++) wv[xr][k] = *(const u64*)&wb[xr * 5 + k];
#pragma unroll
                    for (int kx = 0; kx < 5; kx++) {
                        u64 w = wv[xr][kx];
#pragma unroll
                        for (int j = 0; j < 7; j++)
                            acc0[j] = fma2(w, (kx & 1) ? po[j + (kx >> 1)] : pe[j + (kx >> 1)], acc0[j]);
                    }
                }
                if (xr >= 1) {
#pragma unroll
                    for (int kx = 0; kx < 5; kx++) {
                        u64 w = wv[xr - 1][kx];
#pragma unroll
                        for (int j = 0; j < 7; j++)
                            acc1[j] = fma2(w, (kx & 1) ? po[j + (kx >> 1)] : pe[j + (kx >> 1)], acc1[j]);
                    }
                }
            }
        }
        float bv = s_b1[ch];
        float* yrow = s_y1[img] + (ch * 14 + py) * 20 + 7 * h;
#pragma unroll
        for (int j = 0; j < 7; j++) {
            float a0, a1, c0, c1;
            upk(acc0[j], a0, a1); upk(acc1[j], c0, c1);
            float m = fmaxf(fmaxf(a0, a1), fmaxf(c0, c1)) + bv;
            yrow[j] = fmaxf(m, 0.f);
        }
    }
    __syncthreads();

    // ---- conv2 full depth: 160 tasks = (img, ch, pooled row) ----
    if (tid < 160) {
        int img = tid / 80;
        int r2 = tid % 80, ch2 = r2 / 5, py2 = r2 % 5;
        u64 b0[5], b1[5];
#pragma unroll
        for (int j = 0; j < 5; j++) { b0[j] = 0ull; b1[j] = 0ull; }
#pragma unroll 1
        for (int ic = 0; ic < 6; ic++) {
            const float2* wb = s_w2p + (ch2 * 6 + ic) * 25;
            u64 wv[5][5];
#pragma unroll
            for (int xr = 0; xr < 6; xr++) {
                const u64* rp = (const u64*)(s_y1[img] + (ic * 14 + 2 * py2 + xr) * 20);
                u64 pe[7]; float xl[7], xh[7];
#pragma unroll
                for (int m = 0; m < 7; m++) { pe[m] = rp[m]; upk(pe[m], xl[m], xh[m]); }
                u64 po[6];
#pragma unroll
                for (int m = 0; m < 6; m++) po[m] = pk(xh[m], xl[m + 1]);
                if (xr < 5) {
#pragma unroll
                    for (int k = 0; k < 5; k++) wv[xr][k] = *(const u64*)&wb[xr * 5 + k];
#pragma unroll
                    for (int kx = 0; kx < 5; kx++) {
                        u64 w = wv[xr][kx];
#pragma unroll
                        for (int j = 0; j < 5; j++)
                            b0[j] = fma2(w, (kx & 1) ? po[j + (kx >> 1)] : pe[j + (kx >> 1)], b0[j]);
                    }
                }
                if (xr >= 1) {
#pragma unroll
                    for (int kx = 0; kx < 5; kx++) {
                        u64 w = wv[xr - 1][kx];
#pragma unroll
                        for (int j = 0; j < 5; j++)
                            b1[j] = fma2(w, (kx & 1) ? po[j + (kx >> 1)] : pe[j + (kx >> 1)], b1[j]);
                    }
                }
            }
        }
        float bv = s_b2[ch2];
        float* xfp = s_xf[img] + ch2 * 25 + py2 * 5;
        float* gxf = g_xf + (size_t)(b0i + img) * 400 + ch2 * 25 + py2 * 5;
#pragma unroll
        for (int j = 0; j < 5; j++) {
            float a0, a1, c0, c1;
            upk(b0[j], a0, a1); upk(b1[j], c0, c1);
            float v = fmaxf(fmaxf(a0, a1), fmaxf(c0, c1)) + bv;
            v = fmaxf(v, 0.f);
            xfp[j] = v; gxf[j] = v;
        }
    }
    __syncthreads();

    // ---- h = Ws @ xf + bs : 2 img x 10 outputs x 8 lanes = 160 threads ----
    if (tid < 160) {
        int img = tid / 80, r = tid % 80;
        int o = r >> 3, l = r & 7;
        const float* wr = g_T2 + o * 400;
        const float* xfv = s_xf[img];
        float s = 0.f;
        for (int j = l; j < 400; j += 8) s = fmaf(wr[j], xfv[j], s);
        s += __shfl_down_sync(0xffffffffu, s, 4, 8);
        s += __shfl_down_sync(0xffffffffu, s, 2, 8);
        s += __shfl_down_sync(0xffffffffu, s, 1, 8);
        if (l == 0) hs[img][o] = s + g_b3[o];
    }
    __syncthreads();

    // ---- shapes + argmax + routing: 2 threads (one per image) ----
    if (tid < 2) {
        int img = tid, b = b0i + img;
        float sh[4];
#pragma unroll
        for (int c = 0; c < 4; c++) {
            float s = sb4[c];
#pragma unroll
            for (int o = 0; o < 10; o++)
                s = fmaf(fmaxf(hs[img][o], 0.f), sw4[c * 10 + o], s);
            sh[c] = s;
            out[(size_t)b * 4 + c] = s;
        }
        int pred = 0;
        float best = sh[0];
#pragma unroll
        for (int k = 1; k < 4; k++)
            if (sh[k] > best) { best = sh[k]; pred = k; }
        const int widths[4] = {3, 5, 6, 5};
        int w = widths[pred];
        int val = (b << 2) | pred;
        int slot = b & 31;
        for (int c = 0; c < w; c++) atomicMax(&g_last[c * 32 + slot], val);
    }
}

// ---------------------------------------------------------------------------
// out[b][c] = covered(c) ? dot(xf[b], We[e_j[c]][c]) + be : 0
// 192 threads = 32 images x 6 cols, wsel cached from g_We.
// ---------------------------------------------------------------------------
__global__ void __launch_bounds__(192)
k_out(float* __restrict__ out) {
    __shared__ __align__(16) float wsel[6 * 400];
    __shared__ float bsel[6];
    __shared__ int   psel[6];
    int tid = threadIdx.x;
    if (tid < 6) {
        int mx = -1;
#pragma unroll
        for (int s = 0; s < 32; s++) mx = max(mx, g_last[tid * 32 + s]);
        psel[tid] = mx;
        bsel[tid] = (mx >= 0) ? g_be[(mx & 3) * 6 + tid] : 0.f;
    }
    __syncthreads();
    for (int idx = tid; idx < 2400; idx += 192) {
        int c = idx / 400, j = idx - c * 400;
        int p = psel[c];
        wsel[idx] = (p >= 0) ? g_We[((p & 3) * 6 + c) * 400 + j] : 0.f;
    }
    __syncthreads();
    int r = tid / 6, c = tid - r * 6;
    int b = blockIdx.x * 32 + r;
    const float4* xfp = (const float4*)(g_xf + (size_t)b * 400);
    const float4* wr = (const float4*)(wsel + c * 400);
    float s = bsel[c];
    for (int j = 0; j < 100; j++) {
        float4 xv = xfp[j], wv = wr[j];
        s = fmaf(xv.x, wv.x, s);
        s = fmaf(xv.y, wv.y, s);
        s = fmaf(xv.z, wv.z, s);
        s = fmaf(xv.w, wv.w, s);
    }
    out[(size_t)B_TOTAL * 4 + (size_t)b * 6 + c] = s;
}

// ---------------------------------------------------------------------------
extern "C" void kernel_launch(void* const* d_in, const int* in_sizes, int n_in,
                              void* d_out, int out_size) {
    const float* x    = (const float*)d_in[0];
    const float* c1w  = (const float*)d_in[1];
    const float* c1b  = (const float*)d_in[2];
    const float* c2w  = (const float*)d_in[3];
    const float* c2b  = (const float*)d_in[4];
    const float* sw1  = (const float*)d_in[5];
    const float* sb1  = (const float*)d_in[6];
    const float* sw2  = (const float*)d_in[7];
    const float* sb2  = (const float*)d_in[8];
    const float* sw3  = (const float*)d_in[9];
    const float* sb3  = (const float*)d_in[10];
    const float* sw4  = (const float*)d_in[11];
    const float* sb4  = (const float*)d_in[12];
    const float* ew1  = (const float*)d_in[13];
    const float* eb1  = (const float*)d_in[14];
    const float* ew2  = (const float*)d_in[15];
    const float* eb2  = (const float*)d_in[16];
    const float* ew3  = (const float*)d_in[17];
    const float* eb3  = (const float*)d_in[18];
    const float* ew4  = (const float*)d_in[19];
    const float* eb4  = (const float*)d_in[20];
    float* out = (float*)d_out;

    kc_prep<<<80, 256>>>(sw1, sb1, sw2, sb2, sw3, sb3,
                         ew1, eb1, ew2, eb2, ew3, eb3, ew4, eb4);
    k_main<<<B_TOTAL / 2, 192>>>(x, c1w, c1b, c2w, c2b, sw4, sb4, out);
    k_out<<<B_TOTAL / 32, 192>>>(out);
}

// round 10
// speedup vs baseline: 1.0711x; 1.0019x over previous
#include <cuda_runtime.h>
#include <cuda_bf16.h>

// ---------------------------------------------------------------------------
// RtoVMainModel. Convs per image in smem (packed f32x2 FMA); linear heads
// collapsed at runtime (S=W3@W2, T2=S@W1, We=ew4@T2 in kc_prep).
// k_main: 2 images per block, both x resident; conv1 = 336 tasks via
// strided loop (no reload phase); conv2 = 160 tasks; shapes head; routing.
// k_out: gather + 6x400 dots with smem-cached selected expert rows.
// d_out layout: [shapes (B*4) | out (B*6)] float32
// ---------------------------------------------------------------------------

#define B_TOTAL 16384
typedef unsigned long long u64;

__device__ __forceinline__ u64 pk(float lo, float hi) {
    u64 r; asm("mov.b64 %0, {%1, %2};" : "=l"(r) : "f"(lo), "f"(hi)); return r;
}
__device__ __forceinline__ void upk(u64 p, float& lo, float& hi) {
    asm("mov.b64 {%0, %1}, %2;" : "=f"(lo), "=f"(hi) : "l"(p));
}
__device__ __forceinline__ u64 fma2(u64 a, u64 b, u64 c) {
    u64 d; asm("fma.rn.f32x2 %0, %1, %2, %3;" : "=l"(d) : "l"(a), "l"(b), "l"(c)); return d;
}

// scratch (device globals: no allocation allowed)
__device__ float g_T2[5 * 10 * 400];     // chain 0 = shapes head (10x400)
__device__ float g_b3[5 * 10];
__device__ float g_We[4 * 6 * 400];      // expert collapsed rows
__device__ float g_be[4 * 6];            // expert collapsed bias (incl eb4)
__device__ float g_xf[B_TOTAL * 400];    // conv features
__device__ int   g_last[6 * 32];         // routing slots [col][b&31]

// ---------------------------------------------------------------------------
// Prologue: grid = 5 chains x 16 column-chunks = 80 blocks, 256 threads.
// ---------------------------------------------------------------------------
__global__ void __launch_bounds__(256)
kc_prep(const float* __restrict__ sw1, const float* __restrict__ sb1,
        const float* __restrict__ sw2, const float* __restrict__ sb2,
        const float* __restrict__ sw3, const float* __restrict__ sb3,
        const float* __restrict__ ew1, const float* __restrict__ eb1,
        const float* __restrict__ ew2, const float* __restrict__ eb2,
        const float* __restrict__ ew3, const float* __restrict__ eb3,
        const float* __restrict__ ew4, const float* __restrict__ eb4) {
    __shared__ float sW2[84 * 120];
    __shared__ float sW1c[120 * 25];
    __shared__ float sS[10 * 120];
    __shared__ float sb2p[84];
    __shared__ float sT2c[10 * 25];
    __shared__ float sb3l[10];

    int chain = blockIdx.x >> 4, chunk = blockIdx.x & 15;
    int j0 = chunk * 25;
    int tid = threadIdx.x;
    if (blockIdx.x == 0 && tid < 192) g_last[tid] = -1;

    const float* W1 = chain ? (ew1 + (chain - 1) * 120 * 400) : sw1;
    const float* W2 = chain ? (ew2 + (chain - 1) * 84 * 120) : sw2;
    const float* W3 = chain ? (ew3 + (chain - 1) * 10 * 84) : sw3;
    const float* b1 = chain ? (eb1 + (chain - 1) * 120) : sb1;
    const float* b2 = chain ? (eb2 + (chain - 1) * 84) : sb2;
    const float* b3 = chain ? (eb3 + (chain - 1) * 10) : sb3;

    for (int i = tid; i < 10080; i += 256) sW2[i] = W2[i];
    for (int i = tid; i < 3000; i += 256) {
        int row = i / 25, col = i - row * 25;
        sW1c[i] = W1[row * 400 + j0 + col];
    }
    __syncthreads();

    for (int p = tid; p < 1200; p += 256) {
        int o = p / 120, k = p - o * 120;
        float s = 0.f;
        const float* w3r = W3 + o * 84;
        for (int m = 0; m < 84; m++) s = fmaf(w3r[m], sW2[m * 120 + k], s);
        sS[p] = s;
    }
    if (tid < 84) {
        float s = b2[tid];
        const float* r = sW2 + tid * 120;
        for (int k = 0; k < 120; k++) s = fmaf(r[k], b1[k], s);
        sb2p[tid] = s;
    }
    __syncthreads();

    if (tid < 10) {
        float s = b3[tid];
        const float* r = W3 + tid * 84;
        for (int m = 0; m < 84; m++) s = fmaf(r[m], sb2p[m], s);
        sb3l[tid] = s;
        if (chunk == 0) g_b3[chain * 10 + tid] = s;
    }

    if (tid < 250) {
        int o = tid / 25, jj = tid - o * 25;
        float s = 0.f;
        const float* sr = sS + o * 120;
        for (int k = 0; k < 120; k++) s = fmaf(sr[k], sW1c[k * 25 + jj], s);
        g_T2[(chain * 10 + o) * 400 + j0 + jj] = s;
        sT2c[o * 25 + jj] = s;
    }
    __syncthreads();

    if (chain >= 1) {
        int e = chain - 1;
        if (tid < 150) {
            int c = tid / 25, jj = tid - c * 25;
            float s = 0.f;
            const float* w4r = ew4 + e * 60 + c * 10;
#pragma unroll
            for (int k = 0; k < 10; k++) s = fmaf(w4r[k], sT2c[k * 25 + jj], s);
            g_We[(e * 6 + c) * 400 + j0 + jj] = s;
        }
        if (chunk == 0 && tid < 6) {
            float s = eb4[e * 6 + tid];
            const float* w4r = ew4 + e * 60 + tid * 10;
#pragma unroll
            for (int k = 0; k < 10; k++) s = fmaf(w4r[k], sb3l[k], s);
            g_be[e * 6 + tid] = s;
        }
    }
}

// ---------------------------------------------------------------------------
// Main fused kernel: one block (192 threads) per TWO images; both x buffers
// resident; conv1 covers 336 tasks with a strided loop (no barrier inside).
// ---------------------------------------------------------------------------
__global__ void __launch_bounds__(192, 3)
k_main(const float* __restrict__ x,
       const float* __restrict__ c1w, const float* __restrict__ c1b,
       const float* __restrict__ c2w, const float* __restrict__ c2b,
       const float* __restrict__ sw4, const float* __restrict__ sb4,
       float* __restrict__ out) {
    __shared__ __align__(16) float  s_x[2][3 * 32 * 36];
    __shared__ __align__(16) float  s_y1[2][6 * 14 * 20];
    __shared__ __align__(16) float2 s_w1p[450];
    __shared__ __align__(16) float2 s_w2p[2400];
    __shared__ float s_b1[6], s_b2[16];
    __shared__ __align__(16) float s_xf[2][400];
    __shared__ float hs[2][10];

    int b0i = blockIdx.x * 2, tid = threadIdx.x;

    // ---- load both images + weights ----
    {
        const float4* xg = (const float4*)(x + (size_t)b0i * 3072);
        for (int g = tid; g < 1536; g += 192) {
            float4 v = xg[g];
            int im = g / 768, q = g - im * 768;
            int gr = q >> 3, c4 = q & 7;
            *(float4*)(s_x[im] + gr * 36 + c4 * 4) = v;
        }
    }
    for (int i = tid; i < 450; i += 192)  { float w = c1w[i]; s_w1p[i] = make_float2(w, w); }
    for (int i = tid; i < 2400; i += 192) { float w = c2w[i]; s_w2p[i] = make_float2(w, w); }
    if (tid < 6)  s_b1[tid] = c1b[tid];
    if (tid < 16) s_b2[tid] = c2b[tid];
    __syncthreads();

    // ---- conv1 + relu + pool: 336 tasks = (img, ch, pooled row, half) ----
#pragma unroll 1
    for (int t = tid; t < 336; t += 192) {
        int img = t / 168, rem = t % 168;
        int ch = rem / 28, rr = rem % 28, py = rr >> 1, h = rr & 1;
        u64 acc0[7], acc1[7];
#pragma unroll
        for (int j = 0; j < 7; j++) { acc0[j] = 0ull; acc1[j] = 0ull; }
        const float* xbase = s_x[img] + (2 * py) * 36 + 14 * h;
#pragma unroll 1
        for (int ic = 0; ic < 3; ic++) {
            const float2* wb = s_w1p + (ch * 3 + ic) * 25;
            u64 wv[5][5];
#pragma unroll
            for (int xr = 0; xr < 6; xr++) {
                const u64* rp = (const u64*)(xbase + ic * (32 * 36) + xr * 36);
                u64 pe[9]; float xl[9], xh[9];
#pragma unroll
                for (int m = 0; m < 9; m++) { pe[m] = rp[m]; upk(pe[m], xl[m], xh[m]); }
                u64 po[8];
#pragma unroll
                for (int m = 0; m < 8; m++) po[m] = pk(xh[m], xl[m + 1]);
                if (xr < 5) {
#pragma unroll
                    for (int k = 0; k < 5; k++) wv[xr][k] = *(const u64*)&wb[xr * 5 + k];
#pragma unroll
                    for (int kx = 0; kx < 5; kx++) {
                        u64 w = wv[xr][kx];
#pragma unroll
                        for (int j = 0; j < 7; j++)
                            acc0[j] = fma2(w, (kx & 1) ? po[j + (kx >> 1)] : pe[j + (kx >> 1)], acc0[j]);
                    }
                }
                if (xr >= 1) {
#pragma unroll
                    for (int kx = 0; kx < 5; kx++) {
                        u64 w = wv[xr - 1][kx];
#pragma unroll
                        for (int j = 0; j < 7; j++)
                            acc1[j] = fma2(w, (kx & 1) ? po[j + (kx >> 1)] : pe[j + (kx >> 1)], acc1[j]);
                    }
                }
            }
        }
        float bv = s_b1[ch];
        float* yrow = s_y1[img] + (ch * 14 + py) * 20 + 7 * h;
#pragma unroll
        for (int j = 0; j < 7; j++) {
            float a0, a1, c0, c1;
            upk(acc0[j], a0, a1); upk(acc1[j], c0, c1);
            float m = fmaxf(fmaxf(a0, a1), fmaxf(c0, c1)) + bv;
            yrow[j] = fmaxf(m, 0.f);
        }
    }
    __syncthreads();

    // ---- conv2 full depth: 160 tasks = (img, ch, pooled row) ----
    if (tid < 160) {
        int img = tid / 80;
        int r2 = tid % 80, ch2 = r2 / 5, py2 = r2 % 5;
        u64 b0[5], b1[5];
#pragma unroll
        for (int j = 0; j < 5; j++) { b0[j] = 0ull; b1[j] = 0ull; }
#pragma unroll 1
        for (int ic = 0; ic < 6; ic++) {
            const float2* wb = s_w2p + (ch2 * 6 + ic) * 25;
            u64 wv[5][5];
#pragma unroll
            for (int xr = 0; xr < 6; xr++) {
                const u64* rp = (const u64*)(s_y1[img] + (ic * 14 + 2 * py2 + xr) * 20);
                u64 pe[7]; float xl[7], xh[7];
#pragma unroll
                for (int m = 0; m < 7; m++) { pe[m] = rp[m]; upk(pe[m], xl[m], xh[m]); }
                u64 po[6];
#pragma unroll
                for (int m = 0; m < 6; m++) po[m] = pk(xh[m], xl[m + 1]);
                if (xr < 5) {
#pragma unroll
                    for (int k = 0; k < 5; k++) wv[xr][k] = *(const u64*)&wb[xr * 5 + k];
#pragma unroll
                    for (int kx = 0; kx < 5; kx++) {
                        u64 w = wv[xr][kx];
#pragma unroll
                        for (int j = 0; j < 5; j++)
                            b0[j] = fma2(w, (kx & 1) ? po[j + (kx >> 1)] : pe[j + (kx >> 1)], b0[j]);
                    }
                }
                if (xr >= 1) {
#pragma unroll
                    for (int kx = 0; kx < 5; kx++) {
                        u64 w = wv[xr - 1][kx];
#pragma unroll
                        for (int j = 0; j < 5; j++)
                            b1[j] = fma2(w, (kx & 1) ? po[j + (kx >> 1)] : pe[j + (kx >> 1)], b1[j]);
                    }
                }
            }
        }
        float bv = s_b2[ch2];
        float* xfp = s_xf[img] + ch2 * 25 + py2 * 5;
        float* gxf = g_xf + (size_t)(b0i + img) * 400 + ch2 * 25 + py2 * 5;
#pragma unroll
        for (int j = 0; j < 5; j++) {
            float a0, a1, c0, c1;
            upk(b0[j], a0, a1); upk(b1[j], c0, c1);
            float v = fmaxf(fmaxf(a0, a1), fmaxf(c0, c1)) + bv;
            v = fmaxf(v, 0.f);
            xfp[j] = v; gxf[j] = v;
        }
    }
    __syncthreads();

    // ---- h = Ws @ xf + bs : 2 img x 10 outputs x 8 lanes = 160 threads ----
    if (tid < 160) {
        int img = tid / 80, r = tid % 80;
        int o = r >> 3, l = r & 7;
        const float* wr = g_T2 + o * 400;
        const float* xfv = s_xf[img];
        float s = 0.f;
        for (int j = l; j < 400; j += 8) s = fmaf(wr[j], xfv[j], s);
        s += __shfl_down_sync(0xffffffffu, s, 4, 8);
        s += __shfl_down_sync(0xffffffffu, s, 2, 8);
        s += __shfl_down_sync(0xffffffffu, s, 1, 8);
        if (l == 0) hs[img][o] = s + g_b3[o];
    }
    __syncthreads();

    // ---- shapes + argmax + routing: 2 threads (one per image) ----
    if (tid < 2) {
        int img = tid, b = b0i + img;
        float sh[4];
#pragma unroll
        for (int c = 0; c < 4; c++) {
            float s = sb4[c];
#pragma unroll
            for (int o = 0; o < 10; o++)
                s = fmaf(fmaxf(hs[img][o], 0.f), sw4[c * 10 + o], s);
            sh[c] = s;
            out[(size_t)b * 4 + c] = s;
        }
        int pred = 0;
        float best = sh[0];
#pragma unroll
        for (int k = 1; k < 4; k++)
            if (sh[k] > best) { best = sh[k]; pred = k; }
        const int widths[4] = {3, 5, 6, 5};
        int w = widths[pred];
        int val = (b << 2) | pred;
        int slot = b & 31;
        for (int c = 0; c < w; c++) atomicMax(&g_last[c * 32 + slot], val);
    }
}

// ---------------------------------------------------------------------------
// out[b][c] = covered(c) ? dot(xf[b], We[e_j[c]][c]) + be : 0
// 192 threads = 32 images x 6 cols, wsel cached from g_We.
// ---------------------------------------------------------------------------
__global__ void __launch_bounds__(192)
k_out(float* __restrict__ out) {
    __shared__ __align__(16) float wsel[6 * 400];
    __shared__ float bsel[6];
    __shared__ int   psel[6];
    int tid = threadIdx.x;
    if (tid < 6) {
        int mx = -1;
#pragma unroll
        for (int s = 0; s < 32; s++) mx = max(mx, g_last[tid * 32 + s]);
        psel[tid] = mx;
        bsel[tid] = (mx >= 0) ? g_be[(mx & 3) * 6 + tid] : 0.f;
    }
    __syncthreads();
    for (int idx = tid; idx < 2400; idx += 192) {
        int c = idx / 400, j = idx - c * 400;
        int p = psel[c];
        wsel[idx] = (p >= 0) ? g_We[((p & 3) * 6 + c) * 400 + j] : 0.f;
    }
    __syncthreads();
    int r = tid / 6, c = tid - r * 6;
    int b = blockIdx.x * 32 + r;
    const float4* xfp = (const float4*)(g_xf + (size_t)b * 400);
    const float4* wr = (const float4*)(wsel + c * 400);
    float s = bsel[c];
    for (int j = 0; j < 100; j++) {
        float4 xv = xfp[j], wv = wr[j];
        s = fmaf(xv.x, wv.x, s);
        s = fmaf(xv.y, wv.y, s);
        s = fmaf(xv.z, wv.z, s);
        s = fmaf(xv.w, wv.w, s);
    }
    out[(size_t)B_TOTAL * 4 + (size_t)b * 6 + c] = s;
}

// ---------------------------------------------------------------------------
extern "C" void kernel_launch(void* const* d_in, const int* in_sizes, int n_in,
                              void* d_out, int out_size) {
    const float* x    = (const float*)d_in[0];
    const float* c1w  = (const float*)d_in[1];
    const float* c1b  = (const float*)d_in[2];
    const float* c2w  = (const float*)d_in[3];
    const float* c2b  = (const float*)d_in[4];
    const float* sw1  = (const float*)d_in[5];
    const float* sb1  = (const float*)d_in[6];
    const float* sw2  = (const float*)d_in[7];
    const float* sb2  = (const float*)d_in[8];
    const float* sw3  = (const float*)d_in[9];
    const float* sb3  = (const float*)d_in[10];
    const float* sw4  = (const float*)d_in[11];
    const float* sb4  = (const float*)d_in[12];
    const float* ew1  = (const float*)d_in[13];
    const float* eb1  = (const float*)d_in[14];
    const float* ew2  = (const float*)d_in[15];
    const float* eb2  = (const float*)d_in[16];
    const float* ew3  = (const float*)d_in[17];
    const float* eb3  = (const float*)d_in[18];
    const float* ew4  = (const float*)d_in[19];
    const float* eb4  = (const float*)d_in[20];
    float* out = (float*)d_out;

    kc_prep<<<80, 256>>>(sw1, sb1, sw2, sb2, sw3, sb3,
                         ew1, eb1, ew2, eb2, ew3, eb3, ew4, eb4);
    k_main<<<B_TOTAL / 2, 192>>>(x, c1w, c1b, c2w, c2b, sw4, sb4, out);
    k_out<<<B_TOTAL / 32, 192>>>(out);
}

// round 11
// speedup vs baseline: 1.0810x; 1.0092x over previous
#include <cuda_runtime.h>
#include <cuda_bf16.h>

// ---------------------------------------------------------------------------
// RtoVMainModel. Convs per image in smem (packed f32x2 FMA); linear heads
// collapsed at runtime (S=W3@W2, T2=S@W1, We=ew4@T2) by PREP BLOCKS fused
// into the main grid (blocks 0-79). Conv blocks (80..8271) spin on a 16-count
// flag before the head phase (chain-0 outputs); k_out gathers expert rows.
// d_out layout: [shapes (B*4) | out (B*6)] float32
// ---------------------------------------------------------------------------

#define B_TOTAL 16384
typedef unsigned long long u64;

__device__ __forceinline__ u64 pk(float lo, float hi) {
    u64 r; asm("mov.b64 %0, {%1, %2};" : "=l"(r) : "f"(lo), "f"(hi)); return r;
}
__device__ __forceinline__ void upk(u64 p, float& lo, float& hi) {
    asm("mov.b64 {%0, %1}, %2;" : "=f"(lo), "=f"(hi) : "l"(p));
}
__device__ __forceinline__ u64 fma2(u64 a, u64 b, u64 c) {
    u64 d; asm("fma.rn.f32x2 %0, %1, %2, %3;" : "=l"(d) : "l"(a), "l"(b), "l"(c)); return d;
}

// scratch (device globals: no allocation allowed)
__device__ float g_T2[5 * 10 * 400];     // chain 0 = shapes head (10x400)
__device__ float g_b3[5 * 10];
__device__ float g_We[4 * 6 * 400];      // expert collapsed rows
__device__ float g_be[4 * 6];            // expert collapsed bias (incl eb4)
__device__ float g_xf[B_TOTAL * 400];    // conv features
__device__ int   g_last[6 * 32];         // routing slots [col][b&31]
__device__ int   g_ready;                // chain-0 prep completion counter

// ---------------------------------------------------------------------------
// Fused kernel: blocks 0-79 = prep (5 chains x 16 column-chunks);
// blocks 80..8271 = conv path, 2 images each.
// ---------------------------------------------------------------------------
__global__ void __launch_bounds__(192, 3)
k_main(const float* __restrict__ x,
       const float* __restrict__ c1w, const float* __restrict__ c1b,
       const float* __restrict__ c2w, const float* __restrict__ c2b,
       const float* __restrict__ sw4, const float* __restrict__ sb4,
       const float* __restrict__ sw1, const float* __restrict__ sb1,
       const float* __restrict__ sw2, const float* __restrict__ sb2,
       const float* __restrict__ sw3, const float* __restrict__ sb3,
       const float* __restrict__ ew1, const float* __restrict__ eb1,
       const float* __restrict__ ew2, const float* __restrict__ eb2,
       const float* __restrict__ ew3, const float* __restrict__ eb3,
       const float* __restrict__ ew4, const float* __restrict__ eb4,
       float* __restrict__ out) {
    __shared__ __align__(16) float  s_x[2][3 * 32 * 36];
    __shared__ __align__(16) float  s_y1[2][6 * 14 * 20];
    __shared__ __align__(16) float2 s_w1p[450];
    __shared__ __align__(16) float2 s_w2p[2400];
    __shared__ float s_b1[6], s_b2[16];
    __shared__ __align__(16) float s_xf[2][400];
    __shared__ float hs[2][10];

    int tid = threadIdx.x;

    // =======================================================================
    // PREP PATH (blocks 0-79)
    // =======================================================================
    if (blockIdx.x < 80) {
        float* sW1c = &s_x[0][0];      // 3000 floats
        float* sS   = sW1c + 3000;     // 1200
        float* sb2p = sS + 1200;       // 84
        float* sT2c = sb2p + 84;       // 250
        float* sb3l = sT2c + 250;      // 10   (total 4544 <= 6912)

        int chain = blockIdx.x >> 4, chunk = blockIdx.x & 15;
        int j0 = chunk * 25;

        if (chain == 0 && tid < 12) g_last[chunk * 12 + tid] = -1;

        const float* W1 = chain ? (ew1 + (chain - 1) * 120 * 400) : sw1;
        const float* W2 = chain ? (ew2 + (chain - 1) * 84 * 120) : sw2;
        const float* W3 = chain ? (ew3 + (chain - 1) * 10 * 84) : sw3;
        const float* b1 = chain ? (eb1 + (chain - 1) * 120) : sb1;
        const float* b2 = chain ? (eb2 + (chain - 1) * 84) : sb2;
        const float* b3 = chain ? (eb3 + (chain - 1) * 10) : sb3;

        for (int i = tid; i < 3000; i += 192) {
            int row = i / 25, col = i - row * 25;
            sW1c[i] = W1[row * 400 + j0 + col];
        }

        // S[o][k] = sum_m W3[o][m] * W2[m][k]  (W2 from global/L2, coalesced)
        for (int p = tid; p < 1200; p += 192) {
            int o = p / 120, k = p - o * 120;
            float s = 0.f;
            const float* w3r = W3 + o * 84;
            for (int m = 0; m < 84; m++) s = fmaf(w3r[m], W2[m * 120 + k], s);
            sS[p] = s;
        }
        if (tid < 84) {
            float s = b2[tid];
            const float* r = W2 + tid * 120;
            for (int k = 0; k < 120; k++) s = fmaf(r[k], b1[k], s);
            sb2p[tid] = s;
        }
        __syncthreads();

        if (tid < 10) {
            float s = b3[tid];
            const float* r = W3 + tid * 84;
            for (int m = 0; m < 84; m++) s = fmaf(r[m], sb2p[m], s);
            sb3l[tid] = s;
            if (chunk == 0) g_b3[chain * 10 + tid] = s;
        }
        __syncthreads();   // sb3l ready for the We-bias stage below

        // T2[o][j0+jj] = sum_k S[o][k] * W1c[k][jj]
        for (int t = tid; t < 250; t += 192) {
            int o = t / 25, jj = t - o * 25;
            float s = 0.f;
            const float* sr = sS + o * 120;
            for (int k = 0; k < 120; k++) s = fmaf(sr[k], sW1c[k * 25 + jj], s);
            g_T2[(chain * 10 + o) * 400 + j0 + jj] = s;
            sT2c[o * 25 + jj] = s;
        }
        __syncthreads();

        if (chain == 0) {
            // signal: g_T2 chain0 + g_b3 chain0 + g_last slice visible
            __threadfence();
            __syncthreads();
            if (tid == 0) atomicAdd(&g_ready, 1);
        } else {
            int e = chain - 1;
            if (tid < 150) {
                int c = tid / 25, jj = tid - c * 25;
                float s = 0.f;
                const float* w4r = ew4 + e * 60 + c * 10;
#pragma unroll
                for (int k = 0; k < 10; k++) s = fmaf(w4r[k], sT2c[k * 25 + jj], s);
                g_We[(e * 6 + c) * 400 + j0 + jj] = s;
            }
            if (chunk == 0 && tid < 6) {
                float s = eb4[e * 6 + tid];
                const float* w4r = ew4 + e * 60 + tid * 10;
#pragma unroll
                for (int k = 0; k < 10; k++) s = fmaf(w4r[k], sb3l[k], s);
                g_be[e * 6 + tid] = s;
            }
        }
        return;
    }

    // =======================================================================
    // CONV PATH (blocks 80..): two images per block
    // =======================================================================
    int b0i = (blockIdx.x - 80) * 2;

    // ---- load both images + weights ----
    {
        const float4* xg = (const float4*)(x + (size_t)b0i * 3072);
        for (int g = tid; g < 1536; g += 192) {
            float4 v = xg[g];
            int im = g / 768, q = g - im * 768;
            int gr = q >> 3, c4 = q & 7;
            *(float4*)(s_x[im] + gr * 36 + c4 * 4) = v;
        }
    }
    for (int i = tid; i < 450; i += 192)  { float w = c1w[i]; s_w1p[i] = make_float2(w, w); }
    for (int i = tid; i < 2400; i += 192) { float w = c2w[i]; s_w2p[i] = make_float2(w, w); }
    if (tid < 6)  s_b1[tid] = c1b[tid];
    if (tid < 16) s_b2[tid] = c2b[tid];
    __syncthreads();

    // ---- conv1 + relu + pool: 336 tasks = (img, ch, pooled row, half) ----
#pragma unroll 1
    for (int t = tid; t < 336; t += 192) {
        int img = t / 168, rem = t % 168;
        int ch = rem / 28, rr = rem % 28, py = rr >> 1, h = rr & 1;
        u64 acc0[7], acc1[7];
#pragma unroll
        for (int j = 0; j < 7; j++) { acc0[j] = 0ull; acc1[j] = 0ull; }
        const float* xbase = s_x[img] + (2 * py) * 36 + 14 * h;
#pragma unroll 1
        for (int ic = 0; ic < 3; ic++) {
            const float2* wb = s_w1p + (ch * 3 + ic) * 25;
            u64 wv[5][5];
#pragma unroll
            for (int xr = 0; xr < 6; xr++) {
                const u64* rp = (const u64*)(xbase + ic * (32 * 36) + xr * 36);
                u64 pe[9]; float xl[9], xh[9];
#pragma unroll
                for (int m = 0; m < 9; m++) { pe[m] = rp[m]; upk(pe[m], xl[m], xh[m]); }
                u64 po[8];
#pragma unroll
                for (int m = 0; m < 8; m++) po[m] = pk(xh[m], xl[m + 1]);
                if (xr < 5) {
#pragma unroll
                    for (int k = 0; k < 5; k++) wv[xr][k] = *(const u64*)&wb[xr * 5 + k];
#pragma unroll
                    for (int kx = 0; kx < 5; kx++) {
                        u64 w = wv[xr][kx];
#pragma unroll
                        for (int j = 0; j < 7; j++)
                            acc0[j] = fma2(w, (kx & 1) ? po[j + (kx >> 1)] : pe[j + (kx >> 1)], acc0[j]);
                    }
                }
                if (xr >= 1) {
#pragma unroll
                    for (int kx = 0; kx < 5; kx++) {
                        u64 w = wv[xr - 1][kx];
#pragma unroll
                        for (int j = 0; j < 7; j++)
                            acc1[j] = fma2(w, (kx & 1) ? po[j + (kx >> 1)] : pe[j + (kx >> 1)], acc1[j]);
                    }
                }
            }
        }
        float bv = s_b1[ch];
        float* yrow = s_y1[img] + (ch * 14 + py) * 20 + 7 * h;
#pragma unroll
        for (int j = 0; j < 7; j++) {
            float a0, a1, c0, c1;
            upk(acc0[j], a0, a1); upk(acc1[j], c0, c1);
            float m = fmaxf(fmaxf(a0, a1), fmaxf(c0, c1)) + bv;
            yrow[j] = fmaxf(m, 0.f);
        }
    }
    __syncthreads();

    // ---- conv2 full depth: 160 tasks = (img, ch, pooled row) ----
    if (tid < 160) {
        int img = tid / 80;
        int r2 = tid % 80, ch2 = r2 / 5, py2 = r2 % 5;
        u64 b0[5], b1[5];
#pragma unroll
        for (int j = 0; j < 5; j++) { b0[j] = 0ull; b1[j] = 0ull; }
#pragma unroll 1
        for (int ic = 0; ic < 6; ic++) {
            const float2* wb = s_w2p + (ch2 * 6 + ic) * 25;
            u64 wv[5][5];
#pragma unroll
            for (int xr = 0; xr < 6; xr++) {
                const u64* rp = (const u64*)(s_y1[img] + (ic * 14 + 2 * py2 + xr) * 20);
                u64 pe[7]; float xl[7], xh[7];
#pragma unroll
                for (int m = 0; m < 7; m++) { pe[m] = rp[m]; upk(pe[m], xl[m], xh[m]); }
                u64 po[6];
#pragma unroll
                for (int m = 0; m < 6; m++) po[m] = pk(xh[m], xl[m + 1]);
                if (xr < 5) {
#pragma unroll
                    for (int k = 0; k < 5; k++) wv[xr][k] = *(const u64*)&wb[xr * 5 + k];
#pragma unroll
                    for (int kx = 0; kx < 5; kx++) {
                        u64 w = wv[xr][kx];
#pragma unroll
                        for (int j = 0; j < 5; j++)
                            b0[j] = fma2(w, (kx & 1) ? po[j + (kx >> 1)] : pe[j + (kx >> 1)], b0[j]);
                    }
                }
                if (xr >= 1) {
#pragma unroll
                    for (int kx = 0; kx < 5; kx++) {
                        u64 w = wv[xr - 1][kx];
#pragma unroll
                        for (int j = 0; j < 5; j++)
                            b1[j] = fma2(w, (kx & 1) ? po[j + (kx >> 1)] : pe[j + (kx >> 1)], b1[j]);
                    }
                }
            }
        }
        float bv = s_b2[ch2];
        float* xfp = s_xf[img] + ch2 * 25 + py2 * 5;
        float* gxf = g_xf + (size_t)(b0i + img) * 400 + ch2 * 25 + py2 * 5;
#pragma unroll
        for (int j = 0; j < 5; j++) {
            float a0, a1, c0, c1;
            upk(b0[j], a0, a1); upk(b1[j], c0, c1);
            float v = fmaxf(fmaxf(a0, a1), fmaxf(c0, c1)) + bv;
            v = fmaxf(v, 0.f);
            xfp[j] = v; gxf[j] = v;
        }
    }

    // ---- wait for chain-0 prep (usually already done by now) ----
    if (tid == 0) {
        while (atomicAdd(&g_ready, 0) < 16) __nanosleep(200);
        __threadfence();
    }
    __syncthreads();

    // ---- h = Ws @ xf + bs : 2 img x 10 outputs x 8 lanes = 160 threads ----
    if (tid < 160) {
        int img = tid / 80, r = tid % 80;
        int o = r >> 3, l = r & 7;
        const float* wr = g_T2 + o * 400;
        const float* xfv = s_xf[img];
        float s = 0.f;
        for (int j = l; j < 400; j += 8) s = fmaf(wr[j], xfv[j], s);
        s += __shfl_down_sync(0xffffffffu, s, 4, 8);
        s += __shfl_down_sync(0xffffffffu, s, 2, 8);
        s += __shfl_down_sync(0xffffffffu, s, 1, 8);
        if (l == 0) hs[img][o] = s + g_b3[o];
    }
    __syncthreads();

    // ---- shapes + argmax + routing: 2 threads (one per image) ----
    if (tid < 2) {
        int img = tid, b = b0i + img;
        float sh[4];
#pragma unroll
        for (int c = 0; c < 4; c++) {
            float s = sb4[c];
#pragma unroll
            for (int o = 0; o < 10; o++)
                s = fmaf(fmaxf(hs[img][o], 0.f), sw4[c * 10 + o], s);
            sh[c] = s;
            out[(size_t)b * 4 + c] = s;
        }
        int pred = 0;
        float best = sh[0];
#pragma unroll
        for (int k = 1; k < 4; k++)
            if (sh[k] > best) { best = sh[k]; pred = k; }
        const int widths[4] = {3, 5, 6, 5};
        int w = widths[pred];
        int val = (b << 2) | pred;
        int slot = b & 31;
        for (int c = 0; c < w; c++) atomicMax(&g_last[c * 32 + slot], val);
    }
}

// ---------------------------------------------------------------------------
// out[b][c] = covered(c) ? dot(xf[b], We[e_j[c]][c]) + be : 0
// 192 threads = 32 images x 6 cols, wsel cached from g_We. Resets g_ready.
// ---------------------------------------------------------------------------
__global__ void __launch_bounds__(192)
k_out(float* __restrict__ out) {
    __shared__ __align__(16) float wsel[6 * 400];
    __shared__ float bsel[6];
    __shared__ int   psel[6];
    int tid = threadIdx.x;
    if (blockIdx.x == 0 && tid == 0) g_ready = 0;   // reset for next graph replay
    if (tid < 6) {
        int mx = -1;
#pragma unroll
        for (int s = 0; s < 32; s++) mx = max(mx, g_last[tid * 32 + s]);
        psel[tid] = mx;
        bsel[tid] = (mx >= 0) ? g_be[(mx & 3) * 6 + tid] : 0.f;
    }
    __syncthreads();
    for (int idx = tid; idx < 2400; idx += 192) {
        int c = idx / 400, j = idx - c * 400;
        int p = psel[c];
        wsel[idx] = (p >= 0) ? g_We[((p & 3) * 6 + c) * 400 + j] : 0.f;
    }
    __syncthreads();
    int r = tid / 6, c = tid - r * 6;
    int b = blockIdx.x * 32 + r;
    const float4* xfp = (const float4*)(g_xf + (size_t)b * 400);
    const float4* wr = (const float4*)(wsel + c * 400);
    float s = bsel[c];
    for (int j = 0; j < 100; j++) {
        float4 xv = xfp[j], wv = wr[j];
        s = fmaf(xv.x, wv.x, s);
        s = fmaf(xv.y, wv.y, s);
        s = fmaf(xv.z, wv.z, s);
        s = fmaf(xv.w, wv.w, s);
    }
    out[(size_t)B_TOTAL * 4 + (size_t)b * 6 + c] = s;
}

// ---------------------------------------------------------------------------
extern "C" void kernel_launch(void* const* d_in, const int* in_sizes, int n_in,
                              void* d_out, int out_size) {
    const float* x    = (const float*)d_in[0];
    const float* c1w  = (const float*)d_in[1];
    const float* c1b  = (const float*)d_in[2];
    const float* c2w  = (const float*)d_in[3];
    const float* c2b  = (const float*)d_in[4];
    const float* sw1  = (const float*)d_in[5];
    const float* sb1  = (const float*)d_in[6];
    const float* sw2  = (const float*)d_in[7];
    const float* sb2  = (const float*)d_in[8];
    const float* sw3  = (const float*)d_in[9];
    const float* sb3  = (const float*)d_in[10];
    const float* sw4  = (const float*)d_in[11];
    const float* sb4  = (const float*)d_in[12];
    const float* ew1  = (const float*)d_in[13];
    const float* eb1  = (const float*)d_in[14];
    const float* ew2  = (const float*)d_in[15];
    const float* eb2  = (const float*)d_in[16];
    const float* ew3  = (const float*)d_in[17];
    const float* eb3  = (const float*)d_in[18];
    const float* ew4  = (const float*)d_in[19];
    const float* eb4  = (const float*)d_in[20];
    float* out = (float*)d_out;

    k_main<<<80 + B_TOTAL / 2, 192>>>(x, c1w, c1b, c2w, c2b, sw4, sb4,
                                      sw1, sb1, sw2, sb2, sw3, sb3,
                                      ew1, eb1, ew2, eb2, ew3, eb3, ew4, eb4,
                                      out);
    k_out<<<B_TOTAL / 32, 192>>>(out);
}